// round 2
// baseline (speedup 1.0000x reference)
#include <cuda_runtime.h>

// HyperMLPPrediction: per-sample MLP 128 -> 512 -> 512 -> 512 -> 128
// z row layout (657024 floats per sample):
//   W0 @ 0       (128x512)   B0 @ 65536  (512)
//   W1 @ 66048   (512x512)   B1 @ 328192 (512)
//   W2 @ 328704  (512x512)   B2 @ 590848 (512)
//   W3 @ 591360  (512x128)   B3 @ 656896 (128)
// Pure HBM streaming: every weight byte read exactly once.

constexpr int BATCH   = 512;
constexpr long long TP = 657024;
constexpr int THREADS = 128;

// One 512-wide layer: DIN inputs from xin (smem), 512 outputs to xout (smem).
// Thread t owns outputs [4t, 4t+4): one float4 (LDG.128) per inner iteration.
template <int DIN, bool RELU>
__device__ __forceinline__ void layer512(const float* __restrict__ w,
                                         const float* __restrict__ bias,
                                         const float* __restrict__ xin,
                                         float* __restrict__ xout,
                                         int t)
{
    float4 acc = *reinterpret_cast<const float4*>(&bias[4 * t]);
    const float4* wrow = reinterpret_cast<const float4*>(&w[4 * t]);
    // stride between consecutive i in float4 units: 512/4 = 128
#pragma unroll 8
    for (int i = 0; i < DIN; i++) {
        float  xv = xin[i];
        float4 wv = wrow[i * 128];
        acc.x = fmaf(xv, wv.x, acc.x);
        acc.y = fmaf(xv, wv.y, acc.y);
        acc.z = fmaf(xv, wv.z, acc.z);
        acc.w = fmaf(xv, wv.w, acc.w);
    }
    if (RELU) {
        acc.x = fmaxf(acc.x, 0.0f);
        acc.y = fmaxf(acc.y, 0.0f);
        acc.z = fmaxf(acc.z, 0.0f);
        acc.w = fmaxf(acc.w, 0.0f);
    }
    *reinterpret_cast<float4*>(&xout[4 * t]) = acc;
}

__global__ void __launch_bounds__(THREADS)
hypermlp_kernel(const float* __restrict__ z,
                const float* __restrict__ xq,
                float* __restrict__ out)
{
    __shared__ float xa[512];
    __shared__ float xb[512];

    const int b = blockIdx.x;
    const int t = threadIdx.x;
    const float* zr = z + (long long)b * TP;

    // Load x_q (128 floats) into smem
    xa[t] = xq[b * 128 + t];
    __syncthreads();

    // Layer 0: 128 -> 512, ReLU
    layer512<128, true>(zr + 0, zr + 65536, xa, xb, t);
    __syncthreads();

    // Layer 1: 512 -> 512, ReLU
    layer512<512, true>(zr + 66048, zr + 328192, xb, xa, t);
    __syncthreads();

    // Layer 2: 512 -> 512, ReLU
    layer512<512, true>(zr + 328704, zr + 590848, xa, xb, t);
    __syncthreads();

    // Layer 3: 512 -> 128, no activation. Thread t owns output t (scalar,
    // coalesced: warp reads 128 contiguous bytes per i).
    {
        const float* w    = zr + 591360;
        const float* bias = zr + 656896;
        float acc = bias[t];
#pragma unroll 8
        for (int i = 0; i < 512; i++)
            acc = fmaf(xb[i], w[i * 128 + t], acc);
        out[b * 128 + t] = acc;
    }
}

extern "C" void kernel_launch(void* const* d_in, const int* in_sizes, int n_in,
                              void* d_out, int out_size)
{
    const float* z  = (const float*)d_in[0];
    const float* xq = (const float*)d_in[1];
    // Defensive: z is the big one (512*657024 elements), x_q is 512*128.
    if (n_in >= 2 && in_sizes[0] < in_sizes[1]) {
        const float* tmp = z; z = xq; xq = tmp;
    }
    hypermlp_kernel<<<BATCH, THREADS>>>(z, xq, (float*)d_out);
}

// round 8
// speedup vs baseline: 1.6630x; 1.6630x over previous
#include <cuda_runtime.h>

// HyperMLPPrediction: per-sample MLP 128 -> 512 -> 512 -> 512 -> 128
// z row layout (657024 floats per sample):
//   W0 @ 0       (128x512)   B0 @ 65536  (512)
//   W1 @ 66048   (512x512)   B1 @ 328192 (512)
//   W2 @ 328704  (512x512)   B2 @ 590848 (512)
//   W3 @ 591360  (512x128)   B3 @ 656896 (128)
// Pure HBM streaming. R3-R8: explicit 16-deep LDG.128 batching to force
// MLP=16 (R2 had regs=32 -> MLP_eff~2-3 -> DRAM stuck at 52%).

constexpr int BATCH   = 512;
constexpr long long TP = 657024;
constexpr int THREADS = 128;

#define FMA4(xs, wv) do {                      \
    acc.x = fmaf((xs), (wv).x, acc.x);         \
    acc.y = fmaf((xs), (wv).y, acc.y);         \
    acc.z = fmaf((xs), (wv).z, acc.z);         \
    acc.w = fmaf((xs), (wv).w, acc.w);         \
} while (0)

// One 512-wide layer: DIN inputs from xin (smem), 512 outputs to xout (smem).
// Thread t owns outputs [4t, 4t+4). Per tile of 16 inputs: issue 16
// independent LDG.E.128 into a register array, then consume.
template <int DIN, bool RELU>
__device__ __forceinline__ void layer512(const float* __restrict__ w,
                                         const float* __restrict__ bias,
                                         const float* __restrict__ xin,
                                         float* __restrict__ xout,
                                         int t)
{
    float4 acc = *reinterpret_cast<const float4*>(&bias[4 * t]);
    const float4* wrow = reinterpret_cast<const float4*>(&w[4 * t]);
    // stride between consecutive i in float4 units: 512/4 = 128
#pragma unroll 1
    for (int i0 = 0; i0 < DIN; i0 += 16) {
        float4 wv[16];
#pragma unroll
        for (int j = 0; j < 16; j++)
            wv[j] = wrow[(i0 + j) * 128];
#pragma unroll
        for (int q = 0; q < 4; q++) {
            float4 xv = *reinterpret_cast<const float4*>(&xin[i0 + 4 * q]);
            FMA4(xv.x, wv[4 * q + 0]);
            FMA4(xv.y, wv[4 * q + 1]);
            FMA4(xv.z, wv[4 * q + 2]);
            FMA4(xv.w, wv[4 * q + 3]);
        }
    }
    if (RELU) {
        acc.x = fmaxf(acc.x, 0.0f);
        acc.y = fmaxf(acc.y, 0.0f);
        acc.z = fmaxf(acc.z, 0.0f);
        acc.w = fmaxf(acc.w, 0.0f);
    }
    *reinterpret_cast<float4*>(&xout[4 * t]) = acc;
}

__global__ void __launch_bounds__(THREADS, 4)
hypermlp_kernel(const float* __restrict__ z,
                const float* __restrict__ xq,
                float* __restrict__ out)
{
    __shared__ float xa[512];
    __shared__ float xb[512];

    const int b = blockIdx.x;
    const int t = threadIdx.x;
    const float* zr = z + (long long)b * TP;

    // Load x_q (128 floats) into smem
    xa[t] = xq[b * 128 + t];
    __syncthreads();

    // Layer 0: 128 -> 512, ReLU
    layer512<128, true>(zr + 0, zr + 65536, xa, xb, t);
    __syncthreads();

    // Layer 1: 512 -> 512, ReLU
    layer512<512, true>(zr + 66048, zr + 328192, xb, xa, t);
    __syncthreads();

    // Layer 2: 512 -> 512, ReLU
    layer512<512, true>(zr + 328704, zr + 590848, xa, xb, t);
    __syncthreads();

    // Layer 3: 512 -> 128, no activation. Thread t owns output t; warp reads
    // 128 contiguous bytes per i. Same 16-deep load batching.
    {
        const float* w    = zr + 591360;
        const float* bias = zr + 656896;
        float acc = bias[t];
#pragma unroll 1
        for (int i0 = 0; i0 < 512; i0 += 16) {
            float wv[16];
#pragma unroll
            for (int j = 0; j < 16; j++)
                wv[j] = w[(i0 + j) * 128 + t];
#pragma unroll
            for (int j = 0; j < 16; j++)
                acc = fmaf(xb[i0 + j], wv[j], acc);
        }
        out[b * 128 + t] = acc;
    }
}

extern "C" void kernel_launch(void* const* d_in, const int* in_sizes, int n_in,
                              void* d_out, int out_size)
{
    const float* z  = (const float*)d_in[0];
    const float* xq = (const float*)d_in[1];
    // Defensive: z is the big one (512*657024 elements), x_q is 512*128.
    if (n_in >= 2 && in_sizes[0] < in_sizes[1]) {
        const float* tmp = z; z = xq; xq = tmp;
    }
    hypermlp_kernel<<<BATCH, THREADS>>>(z, xq, (float*)d_out);
}